// round 16
// baseline (speedup 1.0000x reference)
#include <cuda_runtime.h>
#include <cuda_fp16.h>
#include <cstdint>

// ---------------- problem constants ----------------
#define B_    32
#define S_    2048
#define DIN   512
#define NCH   1024
#define WLD   3072
#define MTOT  (B_*S_)       // 65536
#define KK    1024          // combined K = [x | xprev] (virtual; only x stored)
#define NCHUNK 16

// ---------------- scratch ----------------
__device__ __half g_xh[(size_t)MTOT * DIN];    // 64MB x in fp16 (L2-resident)
__device__ __half g_Bh[2048 * KK];             // grouped/transposed f,z weights (fp16)
__device__ float2 g_part[NCHUNK * B_ * NCH];
__device__ float  g_c [B_ * NCH];
__device__ float  g_q0[B_ * NCH];
__device__ float  g_q1[B_ * NCH];

// ---------------- helpers ----------------
__device__ __forceinline__ float sigmoidf_(float x) {
    return __fdividef(1.0f, 1.0f + __expf(-x));
}
__device__ __forceinline__ float tanhf_(float x) {
    x = fminf(fmaxf(x, -15.0f), 15.0f);
    float e = __expf(-2.0f * x);
    return __fdividef(1.0f - e, 1.0f + e);
}
__device__ __forceinline__ uint32_t smem_u32(const void* p) {
    uint32_t a;
    asm("{ .reg .u64 t; cvta.to.shared.u64 t, %1; cvt.u32.u64 %0, t; }" : "=r"(a) : "l"(p));
    return a;
}

#define LDSM4(r0, r1, r2, r3, addr) \
    asm volatile("ldmatrix.sync.aligned.m8n8.x4.shared.b16 {%0,%1,%2,%3}, [%4];" \
        : "=r"(r0), "=r"(r1), "=r"(r2), "=r"(r3) : "r"(addr))

// ---------------- prep: x -> fp16 ----------------
__global__ __launch_bounds__(128)
void prepA(const float* __restrict__ x) {
    int m = blockIdx.x;
    int q = threadIdx.x;                       // float4 index over 512-wide row
    float4 v = reinterpret_cast<const float4*>(x)[(size_t)m * 128 + q];
    __half2* dst = reinterpret_cast<__half2*>(g_xh) + (size_t)m * 256 + q * 2;
    dst[0] = __floats2half2_rn(v.x, v.y);
    dst[1] = __floats2half2_rn(v.z, v.w);
}

// ---------------- prep: Bh[n'][k]; n' groups of 128 = 64 f + 64 z channels ----------------
__global__ void prepB(const float* __restrict__ W, const float* __restrict__ V) {
    __shared__ float tile[32][33];
    int n0 = blockIdx.x * 32;
    int k0 = blockIdx.y * 32;
    int g  = n0 >> 7, rem = n0 & 127, fz = rem >> 6, c0 = rem & 63;
    int col0 = fz * NCH + g * 64 + c0;
    int tx = threadIdx.x, ty = threadIdx.y;   // block (32, 8)
#pragma unroll
    for (int i = 0; i < 4; i++) {
        int k = k0 + ty + i * 8;
        float v = (k < DIN) ? W[(size_t)k * WLD + col0 + tx]
                            : V[(size_t)(k - DIN) * WLD + col0 + tx];
        tile[ty + i * 8][tx] = v;
    }
    __syncthreads();
#pragma unroll
    for (int i = 0; i < 4; i++) {
        int nl = ty + i * 8;
        g_Bh[(size_t)(n0 + nl) * KK + k0 + tx] = __float2half_rn(tile[tx][nl]);
    }
}

// ---------------- main GEMM (fp16 m16n8k16) + fused activation + chunk scan ----------------
// CTA tile 128(M = one chunk) x 256(N = 128 f + 128 z), BK=64, 4-slot ring, 256 thr.
// 8 warps, warp grid 2m x 4n, warp tile 64x64 (32 MMA per 8 LDSM -> 32 FLOP/smem-byte).
// Stages 0..7: k<512 -> x rows m0+r.  Stages 8..15: k>=512 -> x rows m0+r-1 (xprev),
// zero-filled for the sequence-start row via cp.async src-size 0.
#define BKH     64
#define PADH    72                       // halves per smem row (ldmatrix conflict-free)
#define A_TILE_H (128*PADH)              // 9216 halves  = 18432 B
#define B_TILE_H (256*PADH)              // 18432 halves = 36864 B
#define STAGE_BYTES ((A_TILE_H + B_TILE_H)*2)   // 55296 B
#define OFF_VB_B   221184                // 4*STAGE_BYTES
#define OFF_SEG_B  222208
#define SMEM_BYTES 226304
#define FZ_STRIDE  260

__device__ __forceinline__ void stage_issue(uint32_t sbase, size_t m0, int n0,
                                            int t, int s, int by) {
    const int kb = s * BKH;
    const uint32_t base = sbase + (uint32_t)((s & 3) * STAGE_BYTES);
    // A: 128 rows x 8 16B-chunks = 1024 loads
#pragma unroll
    for (int j = 0; j < 4; j++) {
        int idx = t + j * 256;
        int r = idx >> 3, q = idx & 7;
        uint32_t dst = base + (uint32_t)(r * PADH + q * 8) * 2;
        const __half* src;
        uint32_t ssz = 16;
        if (kb < DIN) {
            src = &g_xh[(m0 + r) * DIN + kb + q * 8];
        } else {
            bool zr = (r == 0) && ((by & 15) == 0);   // sequence start: xprev = 0
            src = zr ? g_xh : &g_xh[(m0 + r - 1) * DIN + (kb - DIN) + q * 8];
            ssz = zr ? 0u : 16u;
        }
        asm volatile("cp.async.cg.shared.global [%0], [%1], 16, %2;"
                     :: "r"(dst), "l"(src), "r"(ssz));
    }
    // B: 256 rows x 8 chunks = 2048 loads
#pragma unroll
    for (int j = 0; j < 8; j++) {
        int idx = t + j * 256;
        int r = idx >> 3, q = idx & 7;
        uint32_t dst = base + A_TILE_H * 2 + (uint32_t)(r * PADH + q * 8) * 2;
        const __half* src = &g_Bh[(size_t)(n0 + r) * KK + kb + q * 8];
        asm volatile("cp.async.cg.shared.global [%0], [%1], 16;" :: "r"(dst), "l"(src));
    }
    asm volatile("cp.async.commit_group;");
}

__global__ __launch_bounds__(256, 1)
void gemm_qrnn(const float* __restrict__ Vb) {
    extern __shared__ float sm[];
    const uint32_t sbase = smem_u32(sm);
    const int t = threadIdx.x, lane = t & 31, w = t >> 5;
    const int bx = blockIdx.x, by = blockIdx.y;
    const size_t m0 = (size_t)by * 128;
    const int n0 = bx * 256;
    float* sVb = reinterpret_cast<float*>(reinterpret_cast<char*>(sm) + OFF_VB_B);

    if (t < 128) sVb[t] = Vb[bx * 128 + t];
    else         sVb[t] = Vb[NCH + bx * 128 + (t - 128)];

    const int wm = (w >> 2) * 64, wn = (w & 3) * 64;
    const int rh = lane >> 2, cl = lane & 3;

    float acc[4][8][4];
#pragma unroll
    for (int mi = 0; mi < 4; mi++)
#pragma unroll
        for (int ni = 0; ni < 8; ni++)
#pragma unroll
            for (int j = 0; j < 4; j++) acc[mi][ni][j] = 0.0f;

    // ldmatrix lane addressing
    const uint32_t a_row = (uint32_t)(lane & 15);
    const uint32_t a_koff = (uint32_t)((lane >> 4) << 3);
    const uint32_t b_row = (uint32_t)(((lane >> 4) << 3) + (lane & 7));
    const uint32_t b_koff = (uint32_t)(((lane >> 3) & 1) << 3);

    stage_issue(sbase, m0, n0, t, 0, by);
    stage_issue(sbase, m0, n0, t, 1, by);
    stage_issue(sbase, m0, n0, t, 2, by);

    const int NS = KK / BKH;             // 16 stages
    for (int s = 0; s < NS; s++) {
        if (s < NS - 2)       asm volatile("cp.async.wait_group 2;");
        else if (s == NS - 2) asm volatile("cp.async.wait_group 1;");
        else                  asm volatile("cp.async.wait_group 0;");
        __syncthreads();     // all warps done reading slot (s-1)&3; stage s resident

        if (s + 3 < NS) stage_issue(sbase, m0, n0, t, s + 3, by);   // writes slot (s-1)&3

        const uint32_t Ab = sbase + (uint32_t)((s & 3) * STAGE_BYTES);
        const uint32_t Bb = Ab + A_TILE_H * 2;
#pragma unroll
        for (int k16 = 0; k16 < 4; k16++) {
            const uint32_t kb = k16 * 16;
            uint32_t a[4][4], b[8][2];
#pragma unroll
            for (int mi = 0; mi < 4; mi++) {
                uint32_t addr = Ab + ((wm + mi * 16 + a_row) * PADH + kb + a_koff) * 2;
                LDSM4(a[mi][0], a[mi][1], a[mi][2], a[mi][3], addr);
            }
#pragma unroll
            for (int nip = 0; nip < 4; nip++) {
                uint32_t addr = Bb + ((wn + nip * 16 + b_row) * PADH + kb + b_koff) * 2;
                LDSM4(b[2 * nip][0], b[2 * nip][1], b[2 * nip + 1][0], b[2 * nip + 1][1], addr);
            }
#pragma unroll
            for (int mi = 0; mi < 4; mi++)
#pragma unroll
                for (int ni = 0; ni < 8; ni++)
                    asm volatile(
                        "mma.sync.aligned.m16n8k16.row.col.f32.f16.f16.f32 "
                        "{%0,%1,%2,%3}, {%4,%5,%6,%7}, {%8,%9}, {%0,%1,%2,%3};"
                        : "+f"(acc[mi][ni][0]), "+f"(acc[mi][ni][1]),
                          "+f"(acc[mi][ni][2]), "+f"(acc[mi][ni][3])
                        : "r"(a[mi][0]), "r"(a[mi][1]), "r"(a[mi][2]), "r"(a[mi][3]),
                          "r"(b[ni][0]), "r"(b[ni][1]));
        }
    }
    __syncthreads();

    // ---- epilogue: raw pre -> smem tile [128 t][256 ch] (stride 260 floats) ----
    float* fz = sm;
#pragma unroll
    for (int mi = 0; mi < 4; mi++) {
        int row = wm + mi * 16 + rh;
#pragma unroll
        for (int ni = 0; ni < 8; ni++) {
            int col = wn + ni * 8 + cl * 2;
            *reinterpret_cast<float2*>(&fz[row * FZ_STRIDE + col]) =
                make_float2(acc[mi][ni][0], acc[mi][ni][1]);
            *reinterpret_cast<float2*>(&fz[(row + 8) * FZ_STRIDE + col]) =
                make_float2(acc[mi][ni][2], acc[mi][ni][3]);
        }
    }
    __syncthreads();

    // ---- activations + 2x64-step serial segment scan (256 thr = 2 seg x 128 ch) ----
    {
        const int c = t & 127, seg = t >> 7;
        const int fcol = (c >> 6) * 128 + (c & 63);
        const int zcol = fcol + 64;
        const float bf = sVb[c], bz = sVb[128 + c];
        float P = 1.0f, C = 0.0f;
#pragma unroll 4
        for (int i = 0; i < 64; i++) {
            int tt = seg * 64 + i;
            float f = sigmoidf_(fz[tt * FZ_STRIDE + fcol] + bf);
            float z = (1.0f - f) * tanhf_(fz[tt * FZ_STRIDE + zcol] + bz);
            C = fmaf(f, C, z);
            P *= f;
        }
        float2* segS = reinterpret_cast<float2*>(reinterpret_cast<char*>(sm) + OFF_SEG_B);
        segS[seg * 128 + c] = make_float2(P, C);
    }
    __syncthreads();

    if (t < 128) {
        float2* segS = reinterpret_cast<float2*>(reinterpret_cast<char*>(sm) + OFF_SEG_B);
        float2 a0 = segS[t];
        float2 a1 = segS[128 + t];
        float C = fmaf(a1.x, a0.y, a1.y);
        float P = a0.x * a1.x;
        int b = by >> 4, chunk = by & 15;
        g_part[chunk * (B_ * NCH) + b * NCH + bx * 128 + t] = make_float2(P, C);
    }
}

// ---------------- serial combine over 16 chunks ----------------
__global__ __launch_bounds__(256)
void scan_combine() {
    int i = blockIdx.x * 256 + threadIdx.x;       // 32768
    float c = 0.0f;
#pragma unroll
    for (int ch = 0; ch < NCHUNK; ch++) {
        float2 pc = g_part[ch * (B_ * NCH) + i];
        c = fmaf(pc.x, c, pc.y);
    }
    g_c[i] = c;
}

// ---------------- head: weight-reuse GEMV; one CTA per channel ----------------
__global__ __launch_bounds__(256)
void q_head(const float* __restrict__ x, const float* __restrict__ W,
            const float* __restrict__ V, const float* __restrict__ Vb) {
    __shared__ float wcol[KK];
    int n = blockIdx.x;
    int t = threadIdx.x, lane = t & 31, wrp = t >> 5;
    for (int i = t; i < DIN; i += 256) {
        wcol[i]       = W[(size_t)i * WLD + 2 * NCH + n];
        wcol[DIN + i] = V[(size_t)i * WLD + 2 * NCH + n];
    }
    __syncthreads();
    float bias = Vb[2 * NCH + n];
#pragma unroll
    for (int bb = 0; bb < 4; bb++) {
        int b = wrp * 4 + bb;
        const float* xl = x + (size_t)(b * S_ + S_ - 1) * DIN;
        const float* xp = x + (size_t)(b * S_ + S_ - 2) * DIN;
        float acc = 0.0f;
#pragma unroll 4
        for (int kk = 0; kk < DIN / 32; kk++) {
            acc = fmaf(xl[kk * 32 + lane], wcol[kk * 32 + lane], acc);
            acc = fmaf(xp[kk * 32 + lane], wcol[DIN + kk * 32 + lane], acc);
        }
#pragma unroll
        for (int d = 16; d > 0; d >>= 1)
            acc += __shfl_down_sync(0xffffffffu, acc, d);
        if (lane == 0)
            g_q0[b * NCH + n] = g_c[b * NCH + n] * sigmoidf_(acc + bias);
    }
}

// ---------------- small MLP layers ----------------
__device__ __forceinline__ void mlp_body(const float* __restrict__ in,
                                         const float* __restrict__ Wt,
                                         const float* __restrict__ bias,
                                         float* __restrict__ out,
                                         float* s_in, int Kd, int Nd, bool relu) {
    int b = blockIdx.y, t = threadIdx.x;
    for (int i = t; i < Kd; i += 128) s_in[i] = in[b * Kd + i];
    __syncthreads();
    int n = blockIdx.x * 128 + t;
    float acc = bias[n];
#pragma unroll 8
    for (int k = 0; k < Kd; k++)
        acc = fmaf(s_in[k], Wt[(size_t)k * Nd + n], acc);
    if (relu) acc = fmaxf(acc, 0.0f);
    out[b * Nd + n] = acc;
}
__global__ __launch_bounds__(128) void mlp1(const float* __restrict__ W0, const float* __restrict__ b0)
{ __shared__ float s[NCH]; mlp_body(g_q0, W0, b0, g_q1, s, NCH, NCH, true); }
__global__ __launch_bounds__(128) void mlp2(const float* __restrict__ W1, const float* __restrict__ b1)
{ __shared__ float s[NCH]; mlp_body(g_q1, W1, b1, g_q0, s, NCH, NCH, true); }
__global__ __launch_bounds__(128) void mlp3(const float* __restrict__ W2, const float* __restrict__ b2,
                                            float* __restrict__ out)
{ __shared__ float s[NCH]; mlp_body(g_q0, W2, b2, out, s, NCH, 128, false); }

// ---------------- launcher ----------------
extern "C" void kernel_launch(void* const* d_in, const int* in_sizes, int n_in,
                              void* d_out, int out_size) {
    const float* x  = (const float*)d_in[0];
    const float* W  = (const float*)d_in[1];
    const float* V  = (const float*)d_in[2];
    const float* Vb = (const float*)d_in[3];
    const float* W0 = (const float*)d_in[4];
    const float* b0 = (const float*)d_in[5];
    const float* W1 = (const float*)d_in[6];
    const float* b1 = (const float*)d_in[7];
    const float* W2 = (const float*)d_in[8];
    const float* b2 = (const float*)d_in[9];
    float* out = (float*)d_out;

    cudaFuncSetAttribute(gemm_qrnn, cudaFuncAttributeMaxDynamicSharedMemorySize, SMEM_BYTES);

    prepA<<<MTOT, 128>>>(x);
    prepB<<<dim3(2048 / 32, KK / 32), dim3(32, 8)>>>(W, V);
    gemm_qrnn<<<dim3(8, MTOT / 128), 256, SMEM_BYTES>>>(Vb);
    scan_combine<<<(B_ * NCH) / 256, 256>>>();
    q_head<<<NCH, 256>>>(x, W, V, Vb);
    mlp1<<<dim3(NCH / 128, B_), 128>>>(W0, b0);
    mlp2<<<dim3(NCH / 128, B_), 128>>>(W1, b1);
    mlp3<<<dim3(1, B_), 128>>>(W2, b2, out);
}